// round 7
// baseline (speedup 1.0000x reference)
#include <cuda_runtime.h>
#include <cuda_fp16.h>
#include <cstdint>

// ---------------------------------------------------------------------------
// AUGRU cell, sm_103 base-PTX path (no tcgen05 via compute_103).
// mma.sync.m16n8k16 fp16->fp32, persistent CTAs, fp16 weights resident in
// SMEM (fragment-permuted, conflict-free LDS.32 at base + lane*4).
//
// R7 vs R6: the additive act-block skew (+kt*16) OVERLAPPED adjacent blocks
// (block (mt,7) ran 112B into block (mt+1,0)) -> STS write-write race ->
// rel_err 0.20 in R5/R6. Replaced with an in-block XOR swizzle:
//   element (row,k) @ block(mt,kt)*512 + sub*128 + ((row&7)^kt)*16 + (k&7)*2
// Same bank-conflict immunity, provably no overlap. Applied on staging STS,
// MMA A-fragment LDS, and epilogue h LDS.
// Register prefetch pipeline retained: next tile's x/h LDG'd + converted to
// fp16 regs during current tile's MMA; STS after epilogue; 2 full-CTA
// barriers per tile bound only the fast STS.
//
// Warp map: w = mh*8+ws; mh = 32-row half, ws = 16-col strip.
// acc[gate 0..3][mt 0..1][j 0..1][4]; gates: 0=u, 1=r, 2=x_h, 3=h_h.
// ---------------------------------------------------------------------------

#define HID 128

// SMEM layout (bytes)
#define OFF_WX   0                    // 48 nt * 8 kt * 256 = 98304
#define OFF_WH   98304
#define OFF_BIAS 196608               // 512 floats = 2048
#define OFF_X    198656               // act blocks: (mt*8+kt)*512, 16384 B
#define OFF_H    215040
#define SMEM_TOTAL 231424

static __device__ __forceinline__ uint32_t h2u(__half2 h) {
    return *reinterpret_cast<uint32_t*>(&h);
}

static __device__ __forceinline__ float tanh_fast(float z) {
    float y;
    asm("tanh.approx.f32 %0, %1;" : "=f"(y) : "f"(z));
    return y;
}
static __device__ __forceinline__ float sigmoid_fast(float z) {
    return fmaf(tanh_fast(0.5f * z), 0.5f, 0.5f);
}

static __device__ __forceinline__ void mma16816(float* c, const uint32_t* a,
                                                uint32_t b0, uint32_t b1) {
    asm volatile(
        "mma.sync.aligned.m16n8k16.row.col.f32.f16.f16.f32 "
        "{%0,%1,%2,%3}, {%4,%5,%6,%7}, {%8,%9}, {%0,%1,%2,%3};"
        : "+f"(c[0]), "+f"(c[1]), "+f"(c[2]), "+f"(c[3])
        : "r"(a[0]), "r"(a[1]), "r"(a[2]), "r"(a[3]), "r"(b0), "r"(b1));
}

// act fragment block base (NO skew -- blocks are exactly 512B, disjoint)
static __device__ __forceinline__ uint32_t ablk(int mt, int kt) {
    return (uint32_t)((mt * 8 + kt) * 512);
}

// W fp32 [384,128] row-major -> fp16 B-fragment block layout.
// Block (kt, nt) = 256 B at (nt*8 + kt)*256: [0,128)=b0 (k=2t,2t+1; n=g) at
// (g*4+t)*4; [128,256)=b1 (k=2t+8,2t+9).
static __device__ __forceinline__ void conv_weight(char* smem, uint32_t off,
                                                   const float* __restrict__ W) {
    for (int it = threadIdx.x; it < 384 * 32; it += 512) {
        int n = it >> 5;
        int k4 = (it & 31) << 2;
        float4 v = *reinterpret_cast<const float4*>(W + (size_t)n * 128 + k4);
        __half2 p0 = __floats2half2_rn(v.x, v.y);
        __half2 p1 = __floats2half2_rn(v.z, v.w);
        uint32_t base = off + (uint32_t)(((n >> 3) * 8 + (k4 >> 4)) * 256)
                      + ((k4 & 8) ? 128u : 0u);
        uint32_t o = ((uint32_t)(n & 7) << 4) + ((uint32_t)(k4 & 7) << 1);
        *reinterpret_cast<uint2*>(smem + base + o) = make_uint2(h2u(p0), h2u(p1));
    }
}

__global__ void __launch_bounds__(512, 1) augru_kernel(
    const float* __restrict__ x, const float* __restrict__ h_prev,
    const float* __restrict__ att, const float* __restrict__ Wx,
    const float* __restrict__ bx, const float* __restrict__ Wh,
    const float* __restrict__ bh, float* __restrict__ out, int ntiles)
{
    extern __shared__ char smem[];
    const int tid = threadIdx.x;
    const int w = tid >> 5;
    const int mh = w >> 3;           // 32-row half
    const int ws = w & 7;            // 16-col strip
    const int lane = tid & 31;
    const int g_id = lane >> 2;
    const int t2 = (lane & 3) << 1;

    // prefetch/staging role: row = tid>>3 (0..63), kt chunk = tid&7
    const int prow = tid >> 3;
    const int pkt = tid & 7;
    // XOR swizzle on the 16B granule index within the 128B sub-region
    const uint32_t psts = ablk(prow >> 4, pkt)
                        + (uint32_t)(((prow >> 3) & 1) * 128)
                        + (uint32_t)(((prow & 7) ^ pkt) << 4);

    // ---- one-time: combined biases + fp16 weights ----
    {
        float* sb = reinterpret_cast<float*>(smem + OFF_BIAS);
        if (tid < 128) {
            sb[tid]       = bx[tid] + bh[tid];
            sb[128 + tid] = bx[128 + tid] + bh[128 + tid];
            sb[256 + tid] = bx[256 + tid];
            sb[384 + tid] = bh[256 + tid];
        }
    }
    conv_weight(smem, OFF_WX, Wx);
    conv_weight(smem, OFF_WH, Wh);

    const float* sb = reinterpret_cast<const float*>(smem + OFF_BIAS);
    const int stride = gridDim.x;

    // ---- prologue: stage first tile ----
    int tile = blockIdx.x;
    {
        const float* sx = x + ((size_t)tile * 64 + prow) * 128 + pkt * 16;
        const float* sh = h_prev + ((size_t)tile * 64 + prow) * 128 + pkt * 16;
        float4 a0 = *(const float4*)(sx);     float4 a1 = *(const float4*)(sx + 4);
        float4 a2 = *(const float4*)(sx + 8); float4 a3 = *(const float4*)(sx + 12);
        float4 b0 = *(const float4*)(sh);     float4 b1 = *(const float4*)(sh + 4);
        float4 b2 = *(const float4*)(sh + 8); float4 b3 = *(const float4*)(sh + 12);
        *reinterpret_cast<uint4*>(smem + OFF_X + psts) =
            make_uint4(h2u(__floats2half2_rn(a0.x, a0.y)), h2u(__floats2half2_rn(a0.z, a0.w)),
                       h2u(__floats2half2_rn(a1.x, a1.y)), h2u(__floats2half2_rn(a1.z, a1.w)));
        *reinterpret_cast<uint4*>(smem + OFF_X + psts + 256) =
            make_uint4(h2u(__floats2half2_rn(a2.x, a2.y)), h2u(__floats2half2_rn(a2.z, a2.w)),
                       h2u(__floats2half2_rn(a3.x, a3.y)), h2u(__floats2half2_rn(a3.z, a3.w)));
        *reinterpret_cast<uint4*>(smem + OFF_H + psts) =
            make_uint4(h2u(__floats2half2_rn(b0.x, b0.y)), h2u(__floats2half2_rn(b0.z, b0.w)),
                       h2u(__floats2half2_rn(b1.x, b1.y)), h2u(__floats2half2_rn(b1.z, b1.w)));
        *reinterpret_cast<uint4*>(smem + OFF_H + psts + 256) =
            make_uint4(h2u(__floats2half2_rn(b2.x, b2.y)), h2u(__floats2half2_rn(b2.z, b2.w)),
                       h2u(__floats2half2_rn(b3.x, b3.y)), h2u(__floats2half2_rn(b3.z, b3.w)));
    }
    __syncthreads();

    for (; tile < ntiles; tile += stride) {
        const size_t row0 = (size_t)tile * 64;
        const int nxt = tile + stride;
        const bool hasnext = nxt < ntiles;

        // ---- 1. prefetch next tile -> fp16 regs (hidden behind MMA) ----
        uint32_t pxr[8], phr[8];
        if (hasnext) {
            const float* sx = x + ((size_t)nxt * 64 + prow) * 128 + pkt * 16;
            const float* sh = h_prev + ((size_t)nxt * 64 + prow) * 128 + pkt * 16;
            float4 a0 = *(const float4*)(sx);     float4 a1 = *(const float4*)(sx + 4);
            float4 a2 = *(const float4*)(sx + 8); float4 a3 = *(const float4*)(sx + 12);
            float4 b0 = *(const float4*)(sh);     float4 b1 = *(const float4*)(sh + 4);
            float4 b2 = *(const float4*)(sh + 8); float4 b3 = *(const float4*)(sh + 12);
            pxr[0] = h2u(__floats2half2_rn(a0.x, a0.y)); pxr[1] = h2u(__floats2half2_rn(a0.z, a0.w));
            pxr[2] = h2u(__floats2half2_rn(a1.x, a1.y)); pxr[3] = h2u(__floats2half2_rn(a1.z, a1.w));
            pxr[4] = h2u(__floats2half2_rn(a2.x, a2.y)); pxr[5] = h2u(__floats2half2_rn(a2.z, a2.w));
            pxr[6] = h2u(__floats2half2_rn(a3.x, a3.y)); pxr[7] = h2u(__floats2half2_rn(a3.z, a3.w));
            phr[0] = h2u(__floats2half2_rn(b0.x, b0.y)); phr[1] = h2u(__floats2half2_rn(b0.z, b0.w));
            phr[2] = h2u(__floats2half2_rn(b1.x, b1.y)); phr[3] = h2u(__floats2half2_rn(b1.z, b1.w));
            phr[4] = h2u(__floats2half2_rn(b2.x, b2.y)); phr[5] = h2u(__floats2half2_rn(b2.z, b2.w));
            phr[6] = h2u(__floats2half2_rn(b3.x, b3.y)); phr[7] = h2u(__floats2half2_rn(b3.z, b3.w));
        }

        // ---- 2. init accum with bias ----
        float acc[4][2][2][4];
        #pragma unroll
        for (int g = 0; g < 4; g++)
            #pragma unroll
            for (int j = 0; j < 2; j++) {
                float2 bb = *reinterpret_cast<const float2*>(
                    sb + g * 128 + ws * 16 + j * 8 + t2);
                #pragma unroll
                for (int mt = 0; mt < 2; mt++) {
                    acc[g][mt][j][0] = bb.x; acc[g][mt][j][1] = bb.y;
                    acc[g][mt][j][2] = bb.x; acc[g][mt][j][3] = bb.y;
                }
            }

        // ---- 3. MMA: both tensors per kt ----
        #pragma unroll 1
        for (int kt = 0; kt < 8; kt++) {
            // XOR-swizzled per-lane A-fragment offset (bijective in 128B region)
            const uint32_t lo = (uint32_t)((((lane >> 2) ^ kt) << 4) | ((lane & 3) << 2));
            uint32_t ax[2][4], ah[2][4];
            #pragma unroll
            for (int mt = 0; mt < 2; mt++) {
                uint32_t ab = ablk(mh * 2 + mt, kt) + lo;
                const char* px = smem + OFF_X + ab;
                const char* ph = smem + OFF_H + ab;
                ax[mt][0] = *(const uint32_t*)(px);
                ax[mt][1] = *(const uint32_t*)(px + 128);
                ax[mt][2] = *(const uint32_t*)(px + 256);
                ax[mt][3] = *(const uint32_t*)(px + 384);
                ah[mt][0] = *(const uint32_t*)(ph);
                ah[mt][1] = *(const uint32_t*)(ph + 128);
                ah[mt][2] = *(const uint32_t*)(ph + 256);
                ah[mt][3] = *(const uint32_t*)(ph + 384);
            }
            #pragma unroll
            for (int j = 0; j < 2; j++)
                #pragma unroll
                for (int g = 0; g < 3; g++) {
                    int nt = g * 16 + ws * 2 + j;
                    const char* bxp = smem + OFF_WX + (nt * 8 + kt) * 256 + lane * 4;
                    const char* bhp = smem + OFF_WH + (nt * 8 + kt) * 256 + lane * 4;
                    uint32_t bx0 = *(const uint32_t*)(bxp);
                    uint32_t bx1 = *(const uint32_t*)(bxp + 128);
                    uint32_t bh0 = *(const uint32_t*)(bhp);
                    uint32_t bh1 = *(const uint32_t*)(bhp + 128);
                    int gh = (g == 2) ? 3 : g;
                    #pragma unroll
                    for (int mt = 0; mt < 2; mt++) {
                        mma16816(acc[g][mt][j],  ax[mt], bx0, bx1);
                        mma16816(acc[gh][mt][j], ah[mt], bh0, bh1);
                    }
                }
        }

        // ---- 4. epilogue: h_prev from fp16 h SMEM tile (XOR swizzle) ----
        #pragma unroll
        for (int mt = 0; mt < 2; mt++) {
            int mtg = mh * 2 + mt;
            int r0 = (int)row0 + mtg * 16 + g_id;
            int r1 = r0 + 8;
            float att0 = __ldg(att + r0);
            float att1 = __ldg(att + r1);
            #pragma unroll
            for (int j = 0; j < 2; j++) {
                int c = ws * 16 + j * 8 + t2;
                const char* hb = smem + OFF_H + ablk(mtg, ws)
                               + 2 * j * 128 + ((g_id ^ ws) << 4) + t2 * 2;
                float2 hp0 = __half22float2(*(const __half2*)(hb));
                float2 hp1 = __half22float2(*(const __half2*)(hb + 128));

                float* uu = acc[0][mt][j];
                float* rr = acc[1][mt][j];
                float* xh = acc[2][mt][j];
                float* hh = acc[3][mt][j];

                float u0 = sigmoid_fast(uu[0]), u1 = sigmoid_fast(uu[1]);
                float u2 = sigmoid_fast(uu[2]), u3 = sigmoid_fast(uu[3]);
                float rg0 = sigmoid_fast(rr[0]), rg1 = sigmoid_fast(rr[1]);
                float rg2 = sigmoid_fast(rr[2]), rg3 = sigmoid_fast(rr[3]);
                float ht0 = tanh_fast(fmaf(rg0, hh[0], xh[0]));
                float ht1 = tanh_fast(fmaf(rg1, hh[1], xh[1]));
                float ht2 = tanh_fast(fmaf(rg2, hh[2], xh[2]));
                float ht3 = tanh_fast(fmaf(rg3, hh[3], xh[3]));

                float2 o0, o1;
                o0.x = fmaf(att0 * u0, ht0 - hp0.x, hp0.x);
                o0.y = fmaf(att0 * u1, ht1 - hp0.y, hp0.y);
                o1.x = fmaf(att1 * u2, ht2 - hp1.x, hp1.x);
                o1.y = fmaf(att1 * u3, ht3 - hp1.y, hp1.y);
                *reinterpret_cast<float2*>(out + (size_t)r0 * 128 + c) = o0;
                *reinterpret_cast<float2*>(out + (size_t)r1 * 128 + c) = o1;
            }
        }

        // ---- 5-7. barrier; STS next tile; barrier ----
        __syncthreads();
        if (hasnext) {
            *reinterpret_cast<uint4*>(smem + OFF_X + psts) =
                make_uint4(pxr[0], pxr[1], pxr[2], pxr[3]);
            *reinterpret_cast<uint4*>(smem + OFF_X + psts + 256) =
                make_uint4(pxr[4], pxr[5], pxr[6], pxr[7]);
            *reinterpret_cast<uint4*>(smem + OFF_H + psts) =
                make_uint4(phr[0], phr[1], phr[2], phr[3]);
            *reinterpret_cast<uint4*>(smem + OFF_H + psts + 256) =
                make_uint4(phr[4], phr[5], phr[6], phr[7]);
        }
        __syncthreads();
    }
}

extern "C" void kernel_launch(void* const* d_in, const int* in_sizes, int n_in,
                              void* d_out, int out_size) {
    const float* x   = (const float*)d_in[0];
    const float* h   = (const float*)d_in[1];
    const float* att = (const float*)d_in[2];
    const float* Wx  = (const float*)d_in[3];
    const float* bx  = (const float*)d_in[4];
    const float* Wh  = (const float*)d_in[5];
    const float* bh  = (const float*)d_in[6];
    float* out = (float*)d_out;

    int B = in_sizes[2];
    int ntiles = B / 64;

    cudaFuncSetAttribute(augru_kernel, cudaFuncAttributeMaxDynamicSharedMemorySize,
                         SMEM_TOTAL);

    int grid = 148;
    if (grid > ntiles) grid = ntiles;
    augru_kernel<<<grid, 512, SMEM_TOTAL>>>(x, h, att, Wx, bx, Wh, bh, out, ntiles);
}

// round 8
// speedup vs baseline: 1.0585x; 1.0585x over previous
#include <cuda_runtime.h>
#include <cuda_fp16.h>
#include <cstdint>

// ---------------------------------------------------------------------------
// AUGRU cell, sm_103 base-PTX path (no tcgen05 via compute_103).
// mma.sync.m16n8k16 fp16->fp32, persistent CTAs, fp16 weights resident in
// SMEM (fragment-permuted), activations staged per 64-row tile.
//
// R8 vs R7:
//  * Prefetch pipeline removed (measured: no benefit; LDG latency is not the
//    bottleneck -- the L1tex/SMEM path is). Synchronous staging, ~100 regs.
//  * conv_weight STS had an 8-way bank conflict (warp: n const, k4=4*lane ->
//    all lanes hit 2 banks). Fixed with a granule XOR by kt on the B layout,
//    applied at BOTH conv-write and mma-read. Reads remain conflict-free.
//  * Streaming cache hints: __ldcs on x/h (each byte read once per pass),
//    __stcs on out -- protects resident weights in L2 from the 96MB stream.
//
// Warp map: w = mh*8+ws; mh = 32-row half, ws = 16-col strip.
// acc[gate 0..3][mt 0..1][j 0..1][4]; gates: 0=u, 1=r, 2=x_h, 3=h_h.
// ---------------------------------------------------------------------------

#define HID 128

// SMEM layout (bytes)
#define OFF_WX   0                    // 48 nt * 8 kt * 256 = 98304
#define OFF_WH   98304
#define OFF_BIAS 196608               // 512 floats = 2048
#define OFF_X    198656               // act blocks: (mt*8+kt)*512, 16384 B
#define OFF_H    215040
#define SMEM_TOTAL 231424

static __device__ __forceinline__ uint32_t h2u(__half2 h) {
    return *reinterpret_cast<uint32_t*>(&h);
}

static __device__ __forceinline__ float tanh_fast(float z) {
    float y;
    asm("tanh.approx.f32 %0, %1;" : "=f"(y) : "f"(z));
    return y;
}
static __device__ __forceinline__ float sigmoid_fast(float z) {
    return fmaf(tanh_fast(0.5f * z), 0.5f, 0.5f);
}

static __device__ __forceinline__ void mma16816(float* c, const uint32_t* a,
                                                uint32_t b0, uint32_t b1) {
    asm volatile(
        "mma.sync.aligned.m16n8k16.row.col.f32.f16.f16.f32 "
        "{%0,%1,%2,%3}, {%4,%5,%6,%7}, {%8,%9}, {%0,%1,%2,%3};"
        : "+f"(c[0]), "+f"(c[1]), "+f"(c[2]), "+f"(c[3])
        : "r"(a[0]), "r"(a[1]), "r"(a[2]), "r"(a[3]), "r"(b0), "r"(b1));
}

// act fragment block base (512B blocks, disjoint)
static __device__ __forceinline__ uint32_t ablk(int mt, int kt) {
    return (uint32_t)((mt * 8 + kt) * 512);
}

// W fp32 [384,128] row-major -> fp16 B-fragment block layout, granule-XOR by kt.
// Block (kt, nt) = 256 B at (nt*8 + kt)*256:
//   b0 region [0,128): granule ((n&7)^kt), byte (k&7 within pair)*... :
//     pair p (k=2p,2p+1) of col c lives at granule (c^kt)*16 + p*4
//   b1 region [128,256): same with k-8.
static __device__ __forceinline__ void conv_weight(char* smem, uint32_t off,
                                                   const float* __restrict__ W) {
    for (int it = threadIdx.x; it < 384 * 32; it += 512) {
        int n = it >> 5;
        int k4 = (it & 31) << 2;           // k element index, multiple of 4
        int kt = k4 >> 4;
        float4 v = *reinterpret_cast<const float4*>(W + (size_t)n * 128 + k4);
        __half2 p0 = __floats2half2_rn(v.x, v.y);
        __half2 p1 = __floats2half2_rn(v.z, v.w);
        uint32_t base = off + (uint32_t)(((n >> 3) * 8 + kt) * 256)
                      + ((k4 & 8) ? 128u : 0u);
        uint32_t o = ((uint32_t)((n ^ kt) & 7) << 4) + ((uint32_t)(k4 & 7) << 1);
        *reinterpret_cast<uint2*>(smem + base + o) = make_uint2(h2u(p0), h2u(p1));
    }
}

__global__ void __launch_bounds__(512, 1) augru_kernel(
    const float* __restrict__ x, const float* __restrict__ h_prev,
    const float* __restrict__ att, const float* __restrict__ Wx,
    const float* __restrict__ bx, const float* __restrict__ Wh,
    const float* __restrict__ bh, float* __restrict__ out, int ntiles)
{
    extern __shared__ char smem[];
    const int tid = threadIdx.x;
    const int w = tid >> 5;
    const int mh = w >> 3;           // 32-row half
    const int ws = w & 7;            // 16-col strip
    const int lane = tid & 31;
    const int g_id = lane >> 2;
    const int t2 = (lane & 3) << 1;

    // staging role: row = tid>>3 (0..63), kt chunk = tid&7
    const int prow = tid >> 3;
    const int pkt = tid & 7;
    // XOR swizzle on the 16B granule within the 128B sub-region
    const uint32_t psts = ablk(prow >> 4, pkt)
                        + (uint32_t)(((prow >> 3) & 1) * 128)
                        + (uint32_t)(((prow & 7) ^ pkt) << 4);

    // ---- one-time: combined biases + fp16 weights ----
    {
        float* sb = reinterpret_cast<float*>(smem + OFF_BIAS);
        if (tid < 128) {
            sb[tid]       = bx[tid] + bh[tid];
            sb[128 + tid] = bx[128 + tid] + bh[128 + tid];
            sb[256 + tid] = bx[256 + tid];
            sb[384 + tid] = bh[256 + tid];
        }
    }
    conv_weight(smem, OFF_WX, Wx);
    conv_weight(smem, OFF_WH, Wh);
    __syncthreads();

    const float* sb = reinterpret_cast<const float*>(smem + OFF_BIAS);
    const int stride = gridDim.x;

    for (int tile = blockIdx.x; tile < ntiles; tile += stride) {
        const size_t row0 = (size_t)tile * 64;

        // ---- 1. stage x,h tile: LDG (streaming) -> fp16 -> STS ----
        {
            const float* sx = x + (row0 + prow) * 128 + pkt * 16;
            const float* sh = h_prev + (row0 + prow) * 128 + pkt * 16;
            float4 a0 = __ldcs((const float4*)(sx));
            float4 a1 = __ldcs((const float4*)(sx + 4));
            float4 a2 = __ldcs((const float4*)(sx + 8));
            float4 a3 = __ldcs((const float4*)(sx + 12));
            float4 b0 = __ldcs((const float4*)(sh));
            float4 b1 = __ldcs((const float4*)(sh + 4));
            float4 b2 = __ldcs((const float4*)(sh + 8));
            float4 b3 = __ldcs((const float4*)(sh + 12));
            *reinterpret_cast<uint4*>(smem + OFF_X + psts) =
                make_uint4(h2u(__floats2half2_rn(a0.x, a0.y)), h2u(__floats2half2_rn(a0.z, a0.w)),
                           h2u(__floats2half2_rn(a1.x, a1.y)), h2u(__floats2half2_rn(a1.z, a1.w)));
            *reinterpret_cast<uint4*>(smem + OFF_X + psts + 256) =
                make_uint4(h2u(__floats2half2_rn(a2.x, a2.y)), h2u(__floats2half2_rn(a2.z, a2.w)),
                           h2u(__floats2half2_rn(a3.x, a3.y)), h2u(__floats2half2_rn(a3.z, a3.w)));
            *reinterpret_cast<uint4*>(smem + OFF_H + psts) =
                make_uint4(h2u(__floats2half2_rn(b0.x, b0.y)), h2u(__floats2half2_rn(b0.z, b0.w)),
                           h2u(__floats2half2_rn(b1.x, b1.y)), h2u(__floats2half2_rn(b1.z, b1.w)));
            *reinterpret_cast<uint4*>(smem + OFF_H + psts + 256) =
                make_uint4(h2u(__floats2half2_rn(b2.x, b2.y)), h2u(__floats2half2_rn(b2.z, b2.w)),
                           h2u(__floats2half2_rn(b3.x, b3.y)), h2u(__floats2half2_rn(b3.z, b3.w)));
        }
        __syncthreads();

        // ---- 2. init accum with bias ----
        float acc[4][2][2][4];
        #pragma unroll
        for (int g = 0; g < 4; g++)
            #pragma unroll
            for (int j = 0; j < 2; j++) {
                float2 bb = *reinterpret_cast<const float2*>(
                    sb + g * 128 + ws * 16 + j * 8 + t2);
                #pragma unroll
                for (int mt = 0; mt < 2; mt++) {
                    acc[g][mt][j][0] = bb.x; acc[g][mt][j][1] = bb.y;
                    acc[g][mt][j][2] = bb.x; acc[g][mt][j][3] = bb.y;
                }
            }

        // ---- 3. MMA: both tensors per kt ----
        #pragma unroll 1
        for (int kt = 0; kt < 8; kt++) {
            // XOR-swizzled A-fragment lane offset
            const uint32_t lo = (uint32_t)((((lane >> 2) ^ kt) << 4) | ((lane & 3) << 2));
            // XOR-swizzled B-fragment lane offset (granule ^ kt)
            const uint32_t lob = (uint32_t)((((lane >> 2) ^ kt) << 4) | ((lane & 3) << 2));
            uint32_t ax[2][4], ah[2][4];
            #pragma unroll
            for (int mt = 0; mt < 2; mt++) {
                uint32_t ab = ablk(mh * 2 + mt, kt) + lo;
                const char* px = smem + OFF_X + ab;
                const char* ph = smem + OFF_H + ab;
                ax[mt][0] = *(const uint32_t*)(px);
                ax[mt][1] = *(const uint32_t*)(px + 128);
                ax[mt][2] = *(const uint32_t*)(px + 256);
                ax[mt][3] = *(const uint32_t*)(px + 384);
                ah[mt][0] = *(const uint32_t*)(ph);
                ah[mt][1] = *(const uint32_t*)(ph + 128);
                ah[mt][2] = *(const uint32_t*)(ph + 256);
                ah[mt][3] = *(const uint32_t*)(ph + 384);
            }
            #pragma unroll
            for (int j = 0; j < 2; j++)
                #pragma unroll
                for (int g = 0; g < 3; g++) {
                    int nt = g * 16 + ws * 2 + j;
                    const char* bxp = smem + OFF_WX + (nt * 8 + kt) * 256 + lob;
                    const char* bhp = smem + OFF_WH + (nt * 8 + kt) * 256 + lob;
                    uint32_t bx0 = *(const uint32_t*)(bxp);
                    uint32_t bx1 = *(const uint32_t*)(bxp + 128);
                    uint32_t bh0 = *(const uint32_t*)(bhp);
                    uint32_t bh1 = *(const uint32_t*)(bhp + 128);
                    int gh = (g == 2) ? 3 : g;
                    #pragma unroll
                    for (int mt = 0; mt < 2; mt++) {
                        mma16816(acc[g][mt][j],  ax[mt], bx0, bx1);
                        mma16816(acc[gh][mt][j], ah[mt], bh0, bh1);
                    }
                }
        }

        // ---- 4. epilogue: h_prev from fp16 h SMEM tile (XOR swizzle) ----
        #pragma unroll
        for (int mt = 0; mt < 2; mt++) {
            int mtg = mh * 2 + mt;
            int r0 = (int)row0 + mtg * 16 + g_id;
            int r1 = r0 + 8;
            float att0 = __ldg(att + r0);
            float att1 = __ldg(att + r1);
            #pragma unroll
            for (int j = 0; j < 2; j++) {
                int c = ws * 16 + j * 8 + t2;
                const char* hb = smem + OFF_H + ablk(mtg, ws)
                               + 2 * j * 128 + ((g_id ^ ws) << 4) + t2 * 2;
                float2 hp0 = __half22float2(*(const __half2*)(hb));
                float2 hp1 = __half22float2(*(const __half2*)(hb + 128));

                float* uu = acc[0][mt][j];
                float* rr = acc[1][mt][j];
                float* xh = acc[2][mt][j];
                float* hh = acc[3][mt][j];

                float u0 = sigmoid_fast(uu[0]), u1 = sigmoid_fast(uu[1]);
                float u2 = sigmoid_fast(uu[2]), u3 = sigmoid_fast(uu[3]);
                float rg0 = sigmoid_fast(rr[0]), rg1 = sigmoid_fast(rr[1]);
                float rg2 = sigmoid_fast(rr[2]), rg3 = sigmoid_fast(rr[3]);
                float ht0 = tanh_fast(fmaf(rg0, hh[0], xh[0]));
                float ht1 = tanh_fast(fmaf(rg1, hh[1], xh[1]));
                float ht2 = tanh_fast(fmaf(rg2, hh[2], xh[2]));
                float ht3 = tanh_fast(fmaf(rg3, hh[3], xh[3]));

                float2 o0, o1;
                o0.x = fmaf(att0 * u0, ht0 - hp0.x, hp0.x);
                o0.y = fmaf(att0 * u1, ht1 - hp0.y, hp0.y);
                o1.x = fmaf(att1 * u2, ht2 - hp1.x, hp1.x);
                o1.y = fmaf(att1 * u3, ht3 - hp1.y, hp1.y);
                __stcs(reinterpret_cast<float2*>(out + (size_t)r0 * 128 + c), o0);
                __stcs(reinterpret_cast<float2*>(out + (size_t)r1 * 128 + c), o1);
            }
        }
        __syncthreads();   // SMEM act reads done before next tile's staging
    }
}

extern "C" void kernel_launch(void* const* d_in, const int* in_sizes, int n_in,
                              void* d_out, int out_size) {
    const float* x   = (const float*)d_in[0];
    const float* h   = (const float*)d_in[1];
    const float* att = (const float*)d_in[2];
    const float* Wx  = (const float*)d_in[3];
    const float* bx  = (const float*)d_in[4];
    const float* Wh  = (const float*)d_in[5];
    const float* bh  = (const float*)d_in[6];
    float* out = (float*)d_out;

    int B = in_sizes[2];
    int ntiles = B / 64;

    cudaFuncSetAttribute(augru_kernel, cudaFuncAttributeMaxDynamicSharedMemorySize,
                         SMEM_TOTAL);

    int grid = 148;
    if (grid > ntiles) grid = ntiles;
    augru_kernel<<<grid, 512, SMEM_TOTAL>>>(x, h, att, Wx, bx, Wh, bh, out, ntiles);
}

// round 9
// speedup vs baseline: 1.0631x; 1.0043x over previous
#include <cuda_runtime.h>
#include <cuda_fp16.h>
#include <cstdint>

// ---------------------------------------------------------------------------
// AUGRU cell, sm_103 base-PTX path (no tcgen05 via compute_103).
// mma.sync.m16n8k16 fp16->fp32, persistent CTAs, fp16 weights resident in
// SMEM (fragment-permuted, granule-XOR conflict-free), activations staged
// per 64-row tile into per-half-private fragment blocks.
//
// R9 vs R8:
//  * Bias hoisted to registers (loaded once from global) -- no per-tile LDS.
//  * Epilogue h_prev captured from the MMA loop's h A-fragment at kt==ws --
//    epilogue is fully register-local (no SMEM reads at all).
//  * The two 256-thread halves are provably SMEM-disjoint (own A-blocks, own
//    staged rows, B read-only) -> per-half named barriers (bar.sync 1+mh,256)
//    let the halves run decoupled; one half stages while the other MMAs.
//  * Staggered next-tile prefetch: LDG x -> epilogue (hides latency) ->
//    LDG h -> bar -> STS -> bar. Peak regs ~128, no spill blowup.
//
// Warp map: w = mh*8+ws; mh = 32-row half, ws = 16-col strip.
// acc[gate 0..3][mt 0..1][j 0..1][4]; gates: 0=u, 1=r, 2=x_h, 3=h_h.
// ---------------------------------------------------------------------------

#define HID 128

// SMEM layout (bytes)
#define OFF_WX   0                    // 48 nt * 8 kt * 256 = 98304
#define OFF_WH   98304
#define OFF_X    196608               // act blocks: (mt*8+kt)*512, 16384 B
#define OFF_H    212992
#define SMEM_TOTAL 229376

static __device__ __forceinline__ uint32_t h2u(__half2 h) {
    return *reinterpret_cast<uint32_t*>(&h);
}
static __device__ __forceinline__ __half2 u2h(uint32_t u) {
    return *reinterpret_cast<__half2*>(&u);
}

static __device__ __forceinline__ float tanh_fast(float z) {
    float y;
    asm("tanh.approx.f32 %0, %1;" : "=f"(y) : "f"(z));
    return y;
}
static __device__ __forceinline__ float sigmoid_fast(float z) {
    return fmaf(tanh_fast(0.5f * z), 0.5f, 0.5f);
}

static __device__ __forceinline__ void mma16816(float* c, const uint32_t* a,
                                                uint32_t b0, uint32_t b1) {
    asm volatile(
        "mma.sync.aligned.m16n8k16.row.col.f32.f16.f16.f32 "
        "{%0,%1,%2,%3}, {%4,%5,%6,%7}, {%8,%9}, {%0,%1,%2,%3};"
        : "+f"(c[0]), "+f"(c[1]), "+f"(c[2]), "+f"(c[3])
        : "r"(a[0]), "r"(a[1]), "r"(a[2]), "r"(a[3]), "r"(b0), "r"(b1));
}

static __device__ __forceinline__ void bar_half(int mh) {
    asm volatile("bar.sync %0, %1;" :: "r"(1 + mh), "r"(256) : "memory");
}

// act fragment block base (512B blocks, disjoint)
static __device__ __forceinline__ uint32_t ablk(int mt, int kt) {
    return (uint32_t)((mt * 8 + kt) * 512);
}

// W fp32 [384,128] row-major -> fp16 B-fragment block layout, granule-XOR kt.
static __device__ __forceinline__ void conv_weight(char* smem, uint32_t off,
                                                   const float* __restrict__ W) {
    for (int it = threadIdx.x; it < 384 * 32; it += 512) {
        int n = it >> 5;
        int k4 = (it & 31) << 2;
        int kt = k4 >> 4;
        float4 v = *reinterpret_cast<const float4*>(W + (size_t)n * 128 + k4);
        __half2 p0 = __floats2half2_rn(v.x, v.y);
        __half2 p1 = __floats2half2_rn(v.z, v.w);
        uint32_t base = off + (uint32_t)(((n >> 3) * 8 + kt) * 256)
                      + ((k4 & 8) ? 128u : 0u);
        uint32_t o = ((uint32_t)((n ^ kt) & 7) << 4) + ((uint32_t)(k4 & 7) << 1);
        *reinterpret_cast<uint2*>(smem + base + o) = make_uint2(h2u(p0), h2u(p1));
    }
}

__global__ void __launch_bounds__(512, 1) augru_kernel(
    const float* __restrict__ x, const float* __restrict__ h_prev,
    const float* __restrict__ att, const float* __restrict__ Wx,
    const float* __restrict__ bx, const float* __restrict__ Wh,
    const float* __restrict__ bh, float* __restrict__ out, int ntiles)
{
    extern __shared__ char smem[];
    const int tid = threadIdx.x;
    const int w = tid >> 5;
    const int mh = w >> 3;           // 32-row half
    const int ws = w & 7;            // 16-col strip
    const int lane = tid & 31;
    const int g_id = lane >> 2;
    const int t2 = (lane & 3) << 1;

    // staging role: row = tid>>3 (0..63; half-private), kt chunk = tid&7
    const int prow = tid >> 3;
    const int pkt = tid & 7;
    const uint32_t psts = ablk(prow >> 4, pkt)
                        + (uint32_t)(((prow >> 3) & 1) * 128)
                        + (uint32_t)(((prow & 7) ^ pkt) << 4);

    // ---- one-time: fp16 weights to SMEM; bias to registers ----
    conv_weight(smem, OFF_WX, Wx);
    conv_weight(smem, OFF_WH, Wh);

    float2 breg[4][2];     // [gate][j]: bias pair at cols (c, c+1)
    #pragma unroll
    for (int j = 0; j < 2; j++) {
        int c = ws * 16 + j * 8 + t2;
        breg[0][j] = make_float2(__ldg(bx + c)       + __ldg(bh + c),
                                 __ldg(bx + c + 1)   + __ldg(bh + c + 1));
        breg[1][j] = make_float2(__ldg(bx + 128 + c)     + __ldg(bh + 128 + c),
                                 __ldg(bx + 128 + c + 1) + __ldg(bh + 128 + c + 1));
        breg[2][j] = make_float2(__ldg(bx + 256 + c), __ldg(bx + 256 + c + 1));
        breg[3][j] = make_float2(__ldg(bh + 256 + c), __ldg(bh + 256 + c + 1));
    }

    const int stride = gridDim.x;

    // ---- prologue: stage first tile ----
    int tile = blockIdx.x;
    {
        const float* sx = x + ((size_t)tile * 64 + prow) * 128 + pkt * 16;
        const float* sh = h_prev + ((size_t)tile * 64 + prow) * 128 + pkt * 16;
        float4 a0 = __ldcs((const float4*)(sx));
        float4 a1 = __ldcs((const float4*)(sx + 4));
        float4 a2 = __ldcs((const float4*)(sx + 8));
        float4 a3 = __ldcs((const float4*)(sx + 12));
        float4 b0 = __ldcs((const float4*)(sh));
        float4 b1 = __ldcs((const float4*)(sh + 4));
        float4 b2 = __ldcs((const float4*)(sh + 8));
        float4 b3 = __ldcs((const float4*)(sh + 12));
        *reinterpret_cast<uint4*>(smem + OFF_X + psts) =
            make_uint4(h2u(__floats2half2_rn(a0.x, a0.y)), h2u(__floats2half2_rn(a0.z, a0.w)),
                       h2u(__floats2half2_rn(a1.x, a1.y)), h2u(__floats2half2_rn(a1.z, a1.w)));
        *reinterpret_cast<uint4*>(smem + OFF_X + psts + 256) =
            make_uint4(h2u(__floats2half2_rn(a2.x, a2.y)), h2u(__floats2half2_rn(a2.z, a2.w)),
                       h2u(__floats2half2_rn(a3.x, a3.y)), h2u(__floats2half2_rn(a3.z, a3.w)));
        *reinterpret_cast<uint4*>(smem + OFF_H + psts) =
            make_uint4(h2u(__floats2half2_rn(b0.x, b0.y)), h2u(__floats2half2_rn(b0.z, b0.w)),
                       h2u(__floats2half2_rn(b1.x, b1.y)), h2u(__floats2half2_rn(b1.z, b1.w)));
        *reinterpret_cast<uint4*>(smem + OFF_H + psts + 256) =
            make_uint4(h2u(__floats2half2_rn(b2.x, b2.y)), h2u(__floats2half2_rn(b2.z, b2.w)),
                       h2u(__floats2half2_rn(b3.x, b3.y)), h2u(__floats2half2_rn(b3.z, b3.w)));
    }
    __syncthreads();   // weights + first tiles visible to all

    for (; tile < ntiles; tile += stride) {
        const size_t row0 = (size_t)tile * 64;
        const int nxt = tile + stride;
        const bool hasnext = nxt < ntiles;

        // ---- 1. init accum with register bias ----
        float acc[4][2][2][4];
        #pragma unroll
        for (int g = 0; g < 4; g++)
            #pragma unroll
            for (int j = 0; j < 2; j++) {
                #pragma unroll
                for (int mt = 0; mt < 2; mt++) {
                    acc[g][mt][j][0] = breg[g][j].x; acc[g][mt][j][1] = breg[g][j].y;
                    acc[g][mt][j][2] = breg[g][j].x; acc[g][mt][j][3] = breg[g][j].y;
                }
            }
        uint32_t hs[2][4];   // h fragment for epilogue (captured at kt==ws)

        // ---- 2. MMA: both tensors per kt ----
        #pragma unroll 1
        for (int kt = 0; kt < 8; kt++) {
            const uint32_t lo = (uint32_t)((((lane >> 2) ^ kt) << 4) | ((lane & 3) << 2));
            uint32_t ax[2][4], ah[2][4];
            #pragma unroll
            for (int mt = 0; mt < 2; mt++) {
                uint32_t ab = ablk(mh * 2 + mt, kt) + lo;
                const char* px = smem + OFF_X + ab;
                const char* ph = smem + OFF_H + ab;
                ax[mt][0] = *(const uint32_t*)(px);
                ax[mt][1] = *(const uint32_t*)(px + 128);
                ax[mt][2] = *(const uint32_t*)(px + 256);
                ax[mt][3] = *(const uint32_t*)(px + 384);
                ah[mt][0] = *(const uint32_t*)(ph);
                ah[mt][1] = *(const uint32_t*)(ph + 128);
                ah[mt][2] = *(const uint32_t*)(ph + 256);
                ah[mt][3] = *(const uint32_t*)(ph + 384);
            }
            if (kt == ws) {   // capture h_prev fragment for the epilogue
                #pragma unroll
                for (int mt = 0; mt < 2; mt++)
                    #pragma unroll
                    for (int q = 0; q < 4; q++) hs[mt][q] = ah[mt][q];
            }
            #pragma unroll
            for (int j = 0; j < 2; j++)
                #pragma unroll
                for (int g = 0; g < 3; g++) {
                    int nt = g * 16 + ws * 2 + j;
                    const char* bxp = smem + OFF_WX + (nt * 8 + kt) * 256 + lo;
                    const char* bhp = smem + OFF_WH + (nt * 8 + kt) * 256 + lo;
                    uint32_t bx0 = *(const uint32_t*)(bxp);
                    uint32_t bx1 = *(const uint32_t*)(bxp + 128);
                    uint32_t bh0 = *(const uint32_t*)(bhp);
                    uint32_t bh1 = *(const uint32_t*)(bhp + 128);
                    int gh = (g == 2) ? 3 : g;
                    #pragma unroll
                    for (int mt = 0; mt < 2; mt++) {
                        mma16816(acc[g][mt][j],  ax[mt], bx0, bx1);
                        mma16816(acc[gh][mt][j], ah[mt], bh0, bh1);
                    }
                }
        }

        // ---- 3. prefetch next x (latency hidden by epilogue) ----
        float4 nx0, nx1, nx2, nx3;
        const float* sxn = x + ((size_t)nxt * 64 + prow) * 128 + pkt * 16;
        if (hasnext) {
            nx0 = __ldcs((const float4*)(sxn));
            nx1 = __ldcs((const float4*)(sxn + 4));
            nx2 = __ldcs((const float4*)(sxn + 8));
            nx3 = __ldcs((const float4*)(sxn + 12));
        }

        // ---- 4. epilogue: fully register-local ----
        #pragma unroll
        for (int mt = 0; mt < 2; mt++) {
            int mtg = mh * 2 + mt;
            int r0 = (int)row0 + mtg * 16 + g_id;
            int r1 = r0 + 8;
            float att0 = __ldg(att + r0);
            float att1 = __ldg(att + r1);
            #pragma unroll
            for (int j = 0; j < 2; j++) {
                int c = ws * 16 + j * 8 + t2;
                float2 hp0 = __half22float2(u2h(hs[mt][2 * j]));
                float2 hp1 = __half22float2(u2h(hs[mt][2 * j + 1]));

                float* uu = acc[0][mt][j];
                float* rr = acc[1][mt][j];
                float* xh = acc[2][mt][j];
                float* hh = acc[3][mt][j];

                float u0 = sigmoid_fast(uu[0]), u1 = sigmoid_fast(uu[1]);
                float u2 = sigmoid_fast(uu[2]), u3 = sigmoid_fast(uu[3]);
                float rg0 = sigmoid_fast(rr[0]), rg1 = sigmoid_fast(rr[1]);
                float rg2 = sigmoid_fast(rr[2]), rg3 = sigmoid_fast(rr[3]);
                float ht0 = tanh_fast(fmaf(rg0, hh[0], xh[0]));
                float ht1 = tanh_fast(fmaf(rg1, hh[1], xh[1]));
                float ht2 = tanh_fast(fmaf(rg2, hh[2], xh[2]));
                float ht3 = tanh_fast(fmaf(rg3, hh[3], xh[3]));

                float2 o0, o1;
                o0.x = fmaf(att0 * u0, ht0 - hp0.x, hp0.x);
                o0.y = fmaf(att0 * u1, ht1 - hp0.y, hp0.y);
                o1.x = fmaf(att1 * u2, ht2 - hp1.x, hp1.x);
                o1.y = fmaf(att1 * u3, ht3 - hp1.y, hp1.y);
                __stcs(reinterpret_cast<float2*>(out + (size_t)r0 * 128 + c), o0);
                __stcs(reinterpret_cast<float2*>(out + (size_t)r1 * 128 + c), o1);
            }
        }

        // ---- 5. prefetch next h; per-half barrier; STS; barrier ----
        float4 nh0, nh1, nh2, nh3;
        const float* shn = h_prev + ((size_t)nxt * 64 + prow) * 128 + pkt * 16;
        if (hasnext) {
            nh0 = __ldcs((const float4*)(shn));
            nh1 = __ldcs((const float4*)(shn + 4));
            nh2 = __ldcs((const float4*)(shn + 8));
            nh3 = __ldcs((const float4*)(shn + 12));
        }
        bar_half(mh);          // all this half's warps done reading act blocks
        if (hasnext) {
            *reinterpret_cast<uint4*>(smem + OFF_X + psts) =
                make_uint4(h2u(__floats2half2_rn(nx0.x, nx0.y)), h2u(__floats2half2_rn(nx0.z, nx0.w)),
                           h2u(__floats2half2_rn(nx1.x, nx1.y)), h2u(__floats2half2_rn(nx1.z, nx1.w)));
            *reinterpret_cast<uint4*>(smem + OFF_X + psts + 256) =
                make_uint4(h2u(__floats2half2_rn(nx2.x, nx2.y)), h2u(__floats2half2_rn(nx2.z, nx2.w)),
                           h2u(__floats2half2_rn(nx3.x, nx3.y)), h2u(__floats2half2_rn(nx3.z, nx3.w)));
            *reinterpret_cast<uint4*>(smem + OFF_H + psts) =
                make_uint4(h2u(__floats2half2_rn(nh0.x, nh0.y)), h2u(__floats2half2_rn(nh0.z, nh0.w)),
                           h2u(__floats2half2_rn(nh1.x, nh1.y)), h2u(__floats2half2_rn(nh1.z, nh1.w)));
            *reinterpret_cast<uint4*>(smem + OFF_H + psts + 256) =
                make_uint4(h2u(__floats2half2_rn(nh2.x, nh2.y)), h2u(__floats2half2_rn(nh2.z, nh2.w)),
                           h2u(__floats2half2_rn(nh3.x, nh3.y)), h2u(__floats2half2_rn(nh3.z, nh3.w)));
        }
        bar_half(mh);          // this half's act blocks staged for next tile
    }
}

extern "C" void kernel_launch(void* const* d_in, const int* in_sizes, int n_in,
                              void* d_out, int out_size) {
    const float* x   = (const float*)d_in[0];
    const float* h   = (const float*)d_in[1];
    const float* att = (const float*)d_in[2];
    const float* Wx  = (const float*)d_in[3];
    const float* bx  = (const float*)d_in[4];
    const float* Wh  = (const float*)d_in[5];
    const float* bh  = (const float*)d_in[6];
    float* out = (float*)d_out;

    int B = in_sizes[2];
    int ntiles = B / 64;

    cudaFuncSetAttribute(augru_kernel, cudaFuncAttributeMaxDynamicSharedMemorySize,
                         SMEM_TOTAL);

    int grid = 148;
    if (grid > ntiles) grid = ntiles;
    augru_kernel<<<grid, 512, SMEM_TOTAL>>>(x, h, att, Wx, bx, Wh, bh, out, ntiles);
}